// round 13
// baseline (speedup 1.0000x reference)
#include <cuda_runtime.h>
#include <math.h>

#define C64 64
#define IMG 21
#define SLICES 7
#define DPS 63     // d-values per slice (7*63 = 441)
#define GRID 296   // 2 blocks/SM on 148 SMs -> all co-resident (barrier-safe)
#define NTHR 256

// ---------------- scratch (device globals; no allocations allowed) ----------
__device__ float g_k1s[2 * 441 * 64];                     // k1[b][pos][c]
__device__ float g_a1r[2 * 25 * 25 * 64];                 // att1 post-BN/ReLU [bg][o*64+c]
__device__ __align__(16) float g_Sw[2 * 25 * 64 * 64];    // TRANSPOSED: scores/B [bg][c'][c]
__device__ float g_pm[2 * 25 * SLICES * 64];              // partial max  [bg][slice][c]
__device__ float g_ps[2 * 25 * SLICES * 64];              // partial sum  [bg][slice][c]
__device__ unsigned g_bcnt;                               // barrier counter (returns to 0)
__device__ int g_bflag;                                   // barrier flag (returns to 0: even # of barriers)

// Grid-wide sense-reversing barrier. Senses alternate 1,0,1,0 across the 4
// call sites; counter is reset by the releaser BEFORE flipping the flag, so
// all state returns to {0,0} by kernel end -> deterministic across replays.
__device__ __forceinline__ void gbarrier(int sense) {
    __syncthreads();
    if (threadIdx.x == 0) {
        __threadfence();
        unsigned old = atomicAdd(&g_bcnt, 1u);
        if (old == GRID - 1) {
            g_bcnt = 0;                  // nobody reads the counter while spinning
            __threadfence();
            g_bflag = sense;
        } else {
            while (*(volatile int*)&g_bflag != sense) { }
        }
        __threadfence();
    }
    __syncthreads();
}

// ---------------------------------------------------------------------------
// One persistent kernel, 5 phases / 4 barriers. Phase bodies are the
// measured-fast R8/R11 kernels, re-gridded over 296 blocks.
// ---------------------------------------------------------------------------
__global__ void __launch_bounds__(NTHR) k_all(
    const float* __restrict__ x,  const float* __restrict__ wk,
    const float* __restrict__ bk, const float* __restrict__ w1,
    const float* __restrict__ bng, const float* __restrict__ bnb,
    const float* __restrict__ bnm, const float* __restrict__ bnv,
    const float* __restrict__ w2, const float* __restrict__ b2,
    const float* __restrict__ wv, const float* __restrict__ bv,
    float* __restrict__ out)
{
    __shared__ __align__(16) float S[3456];   // 13.8 KB, aliased per phase
    const int tid = threadIdx.x;
    const int blk = blockIdx.x;

    // ===== Phase 1: k1[b,pos,c] = bk[pos] + sum_cp x[b,cp,pos]*wk[pos,220-c+cp]
    // 221 tiles of 4 (b,pos) units; tid = sub*64 + c.
    {
        float* xcols = S;          // [4][64]
        float* wkr   = S + 256;    // [4][128] (rows padded to 128)
        const int sub = tid >> 6, c = tid & 63;
        for (int t4 = blk; t4 < 221; t4 += GRID) {
            int u = t4 * 4 + sub;            // this thread's (b,pos) unit
            int b = u / 441, pos = u % 441;
            if (u < 882)
                xcols[tid] = x[(b * C64 + c) * 441 + pos];
            for (int t = tid; t < 4 * 127; t += NTHR) {
                int s2 = t / 127, j = t - s2 * 127;
                int u2 = t4 * 4 + s2;
                if (u2 < 882)
                    wkr[s2 * 128 + j] = wk[(u2 % 441) * 441 + 157 + j];
            }
            __syncthreads();
            if (u < 882) {
                float acc = bk[pos];
                const float* wr = &wkr[sub * 128 + 63 - c];
                const float* xc = &xcols[sub * 64];
                #pragma unroll 16
                for (int cp = 0; cp < 64; cp++) acc = fmaf(xc[cp], wr[cp], acc);
                g_k1s[(b * 441 + pos) * 64 + c] = acc;
            }
            __syncthreads();
        }
    }
    gbarrier(1);

    // ===== Phase 2: att1 = w1[g] @ kq, BN+ReLU. 250 units of (bg, oc).
    // kq flat reinterpretation: kq[i][c] = tile.flat[i*64+c], flat[ch*25+ij].
    {
        float* kqs = S;            // [50*64]
        float* w1s = S + 3200;     // [250]
        for (int u = blk; u < 250; u += GRID) {
            int bg = u / 5, oc = u % 5;
            int b = bg / 25, g = bg % 25;
            int ph = g / 5, pw = g % 5;
            for (int t = tid; t < 250; t += NTHR) w1s[t] = w1[g * 1250 + oc * 250 + t];
            for (int f = tid; f < 3200; f += NTHR) {
                int f2 = (f < 1600) ? f : f - 1600;
                int ch = f2 / 25, ij = f2 % 25;
                int row = (ij / 5) * 5 + ph, col = (ij % 5) * 5 + pw;
                float v = 0.f;
                if (row < IMG && col < IMG) {
                    int pos = row * IMG + col;
                    v = (f < 1600) ? x[((b * C64 + ch) * IMG + row) * IMG + col]
                                   : g_k1s[(b * 441 + pos) * 64 + ch];
                }
                kqs[f] = v;
            }
            __syncthreads();
            for (int o = tid; o < 320; o += NTHR) {
                int lrow = o >> 6, c = o & 63;
                const float* wr = &w1s[lrow * 50];
                float acc = 0.f;
                #pragma unroll
                for (int i = 0; i < 50; i++) acc = fmaf(wr[i], kqs[i * 64 + c], acc);
                int orow = oc * 5 + lrow;
                int go = g * 25 + orow;
                float inv = bng[go] * rsqrtf(bnv[go] + 1e-5f);
                float v = (acc - bnm[go]) * inv + bnb[go];
                g_a1r[bg * 1600 + orow * 64 + c] = fmaxf(v, 0.f);
            }
            __syncthreads();
        }
    }
    gbarrier(0);

    // ===== Phase 3: att2 scores + per-slice softmax partials. 350 units (bg, sl).
    {
        float* w2s = S;            // [63*28] stride-28 rows (16B aligned)
        float* b2s = S + 1764;     // [63]
        float* rm  = S + 1828;     // [256]
        float* rs  = S + 2084;     // [256]
        for (int u = blk; u < 350; u += GRID) {
            int bg = u / SLICES, sl = u % SLICES;
            int g = bg % 25;
            int d0 = sl * DPS;
            for (int t = tid; t < DPS * 25; t += NTHR)
                w2s[(t / 25) * 28 + (t % 25)] = w2[g * 11025 + d0 * 25 + t];
            if (tid < DPS) b2s[tid] = b2[g * 441 + d0 + tid];
            __syncthreads();

            const int c = tid & 63, sub = tid >> 6;
            float myA[25];
            const float* ag = &g_a1r[bg * 1600 + c];
            #pragma unroll
            for (int i = 0; i < 25; i++) myA[i] = ag[i * 64];

            float m = -1e30f, s = 0.f;
            const int lo = 220 - c;
            float* swbase = &g_Sw[bg * 4096];
            for (int dd = sub; dd < DPS; dd += 4) {
                const float4* wr4 = reinterpret_cast<const float4*>(&w2s[dd * 28]);
                float val = b2s[dd];
                #pragma unroll
                for (int q = 0; q < 6; q++) {
                    float4 f = wr4[q];
                    val = fmaf(f.x, myA[4 * q],     val);
                    val = fmaf(f.y, myA[4 * q + 1], val);
                    val = fmaf(f.z, myA[4 * q + 2], val);
                    val = fmaf(f.w, myA[4 * q + 3], val);
                }
                val = fmaf(w2s[dd * 28 + 24], myA[24], val);
                unsigned ci = (unsigned)(d0 + dd - lo);
                if (ci < 64u) swbase[ci * 64 + c] = val;   // transposed, written once
                if (val > m) { s = s * __expf(m - val) + 1.f; m = val; }
                else         { s += __expf(val - m); }
            }
            rm[tid] = m; rs[tid] = s;
            __syncthreads();
            if (tid < 64) {
                float M = fmaxf(fmaxf(rm[tid], rm[64 + tid]), fmaxf(rm[128 + tid], rm[192 + tid]));
                float Ssum = 0.f;
                #pragma unroll
                for (int k = 0; k < 4; k++) Ssum += rs[k * 64 + tid] * __expf(rm[k * 64 + tid] - M);
                g_pm[(bg * SLICES + sl) * 64 + tid] = M;
                g_ps[(bg * SLICES + sl) * 64 + tid] = Ssum;
            }
            __syncthreads();
        }
    }
    gbarrier(1);

    // ===== Phase 4: merge partials, normalize transposed windows. 200 units.
    {
        float* Msh = S;            // [64]
        float* Ish = S + 64;       // [64]
        for (int u = blk; u < 200; u += GRID) {
            int bg = u >> 2, chunk = u & 3;
            if (tid < 64) {
                float M = -1e30f;
                #pragma unroll
                for (int k = 0; k < SLICES; k++) M = fmaxf(M, g_pm[(bg * SLICES + k) * 64 + tid]);
                float Ssum = 0.f;
                #pragma unroll
                for (int k = 0; k < SLICES; k++)
                    Ssum += g_ps[(bg * SLICES + k) * 64 + tid] * __expf(g_pm[(bg * SLICES + k) * 64 + tid] - M);
                Msh[tid] = M; Ish[tid] = 1.f / Ssum;
            }
            __syncthreads();
            float* sw = &g_Sw[bg * 4096 + chunk * 1024];
            for (int t = tid; t < 1024; t += NTHR) {
                int cc = t & 63;               // transposed layout: [c'*64 + c]
                sw[t] = __expf(sw[t] - Msh[cc]) * Ish[cc];
            }
            __syncthreads();
        }
    }
    gbarrier(0);

    // ===== Phase 5: final combine. 882 units of (b,h,w); tid = q*64+c.
    {
        float* vsh  = S;           // [64]
        float* part = S + 64;      // [256]
        const int c = tid & 63, q = tid >> 6;
        for (int u = blk; u < 882; u += GRID) {
            int b = u / 441, p = u % 441;
            int h = p / 21, w = p % 21;
            const bool hasv = (h >= 2 && w >= 2);     // uniform per unit
            if (hasv && q == 0) {                     // depthwise 3x3 conv value
                const int y = h - 2, xq = w - 2;
                float acc = bv[c];
                #pragma unroll
                for (int dy = 0; dy < 3; dy++) {
                    int r = y + dy - 1;
                    #pragma unroll
                    for (int dx = 0; dx < 3; dx++) {
                        int cc = xq + dx - 1;
                        if (r >= 0 && cc >= 0)
                            acc = fmaf(x[((b * C64 + c) * IMG + r) * IMG + cc],
                                       wv[c * 9 + dy * 3 + dx], acc);
                    }
                }
                vsh[c] = acc;
            }
            __syncthreads();
            float partial = 0.f;
            if (hasv) {
                const int g = 5 * ((h + 2) % 5) + ((w + 2) % 5);
                const float* Bt = &g_Sw[(b * 25 + g) * 4096];
                #pragma unroll
                for (int j = 0; j < 16; j++) {
                    int cp = q * 16 + j;
                    partial = fmaf(Bt[cp * 64 + c], vsh[cp], partial);  // coalesced
                }
            }
            part[tid] = partial;
            __syncthreads();
            if (q == 0) {
                float res = part[c] + part[64 + c] + part[128 + c] + part[192 + c];
                if (h < 19 && w < 19)
                    res += g_k1s[(b * 441 + (h + 2) * 21 + (w + 2)) * 64 + c];
                out[((b * C64 + c) * IMG + h) * IMG + w] = res;
            }
            __syncthreads();
        }
    }
}

// ---------------------------------------------------------------------------
extern "C" void kernel_launch(void* const* d_in, const int* in_sizes, int n_in,
                              void* d_out, int out_size)
{
    const float* x   = (const float*)d_in[0];
    const float* wk  = (const float*)d_in[1];
    const float* bk  = (const float*)d_in[2];
    const float* w1  = (const float*)d_in[3];
    const float* bng = (const float*)d_in[4];
    const float* bnb = (const float*)d_in[5];
    const float* bnm = (const float*)d_in[6];
    const float* bnv = (const float*)d_in[7];
    const float* w2  = (const float*)d_in[8];
    const float* b2  = (const float*)d_in[9];
    const float* wv  = (const float*)d_in[10];
    const float* bv  = (const float*)d_in[11];
    float* out = (float*)d_out;

    k_all<<<GRID, NTHR>>>(x, wk, bk, w1, bng, bnb, bnm, bnv, w2, b2, wv, bv, out);
}